// round 11
// baseline (speedup 1.0000x reference)
#include <cuda_runtime.h>
#include <cuda_bf16.h>
#include <cstdint>

typedef uint32_t u32; typedef uint64_t u64;

#define NB 128
#define NT 512
#define GSZ 256
#define SS 512
#define HH 1024
#define STG_A 16384
#define STG_B 4096
#define STG_STRIDE (2 * STG_A + 2 * STG_B)   // 40960
#define SMEM_DYN (4 * STG_STRIDE)            // 163840 (2 groups x 2 buffers)

// ---------- persistent device state ----------
__device__ __nv_bfloat16 g_W0h[8388608], g_W0l[8388608];   // [n'=j*4+g][k] (k contig, 2048)
__device__ __nv_bfloat16 g_W1h[8388608], g_W1l[8388608];
__device__ __nv_bfloat16 g_h0h[2][131072], g_h0l[2][131072];
__device__ __nv_bfloat16 g_h1h[2][131072], g_h1l[2][131072];
__device__ float g_sp[128][128];   // [b][cb]
__device__ unsigned g_cnt, g_gen;

// ---------- helpers ----------
__device__ __forceinline__ u32 smem_u32(const void* p) {
    u32 a; asm("{ .reg .u64 t; cvta.to.shared.u64 t, %1; cvt.u32.u64 %0, t; }" : "=r"(a) : "l"(p));
    return a;
}
__device__ __forceinline__ void ldsm4(u32 a, u32& r0, u32& r1, u32& r2, u32& r3) {
    asm volatile("ldmatrix.sync.aligned.m8n8.x4.shared.b16 {%0,%1,%2,%3}, [%4];"
        : "=r"(r0), "=r"(r1), "=r"(r2), "=r"(r3) : "r"(a));
}
__device__ __forceinline__ void mma16816(float* c, const u32* a, u32 b0, u32 b1) {
    asm volatile("mma.sync.aligned.m16n8k16.row.col.f32.bf16.bf16.f32 "
        "{%0,%1,%2,%3}, {%4,%5,%6,%7}, {%8,%9}, {%0,%1,%2,%3};"
        : "+f"(c[0]), "+f"(c[1]), "+f"(c[2]), "+f"(c[3])
        : "r"(a[0]), "r"(a[1]), "r"(a[2]), "r"(a[3]), "r"(b0), "r"(b1));
}
__device__ __forceinline__ u32 pkbf2(float f0, float f1) {  // mem order [f0,f1]
    u32 r; asm("cvt.rn.bf16x2.f32 %0, %1, %2;" : "=r"(r) : "f"(f1), "f"(f0)); return r;
}
__device__ __forceinline__ void cvt8(uint4& hi, uint4& lo, float4 a, float4 b) {
    hi.x = pkbf2(a.x, a.y); hi.y = pkbf2(a.z, a.w);
    hi.z = pkbf2(b.x, b.y); hi.w = pkbf2(b.z, b.w);
    lo.x = pkbf2(a.x - __uint_as_float(hi.x << 16), a.y - __uint_as_float(hi.x & 0xffff0000u));
    lo.y = pkbf2(a.z - __uint_as_float(hi.y << 16), a.w - __uint_as_float(hi.y & 0xffff0000u));
    lo.z = pkbf2(b.x - __uint_as_float(hi.z << 16), b.y - __uint_as_float(hi.z & 0xffff0000u));
    lo.w = pkbf2(b.z - __uint_as_float(hi.w << 16), b.w - __uint_as_float(hi.w & 0xffff0000u));
}
__device__ __forceinline__ void sts16(char* base, int off, uint4 v) {
    *(uint4*)(base + (off ^ ((off >> 3) & 0x70))) = v;
}
__device__ __forceinline__ float sigf(float x) {
    return __fdividef(1.f, 1.f + __expf(-x));
}
__device__ __forceinline__ float tanhfast(float x) {
    return 1.f - __fdividef(2.f, 1.f + __expf(2.f * x));
}

// ---------- init + weight conversion (merged: 2 launches per replay) ----------
__global__ void conv_w(const float* __restrict__ U0, const float* __restrict__ V0,
                       const float* __restrict__ U1, const float* __restrict__ V1) {
    size_t i = (size_t)blockIdx.x * 256 + threadIdx.x;   // 2 * 4096 * 2048
    if (i < 131072) {
        __nv_bfloat16 z = __float2bfloat16(0.f);
        g_h0h[0][i] = z; g_h0l[0][i] = z; g_h1h[0][i] = z; g_h1l[0][i] = z;
    }
    if (i == 0) { g_cnt = 0; g_gen = 0; }
    int layer = (int)(i >> 23);
    size_t r = i & 8388607;
    int np = (int)(r >> 11), k = (int)(r & 2047);
    int g = np & 3, j = np >> 2;
    const float* src = layer ? (k < 1024 ? U1 : V1) : (k < 1024 ? U0 : V0);
    float v = src[(size_t)(k & 1023) * 4096 + g * 1024 + j];
    __nv_bfloat16 hi = __float2bfloat16(v);
    __nv_bfloat16 lo = __float2bfloat16(v - __bfloat162float(hi));
    if (layer) { g_W1h[r] = hi; g_W1l[r] = lo; }
    else       { g_W0h[r] = hi; g_W0l[r] = lo; }
}

// ---------- barriers ----------
__device__ __forceinline__ void gbar_arrive() {
    __syncthreads();
    if (threadIdx.x == 0) {
        __threadfence();
        if (atomicAdd(&g_cnt, 1u) == NB - 1) {
            g_cnt = 0; __threadfence(); atomicAdd(&g_gen, 1u);
        }
    }
}
__device__ __forceinline__ void gbar_wait(unsigned target) {
    if (threadIdx.x == 0) {
        while (*(volatile unsigned*)&g_gen < target) {}
        __threadfence();
    }
    __syncthreads();
}
__device__ __forceinline__ void gsync(int grp) {
    asm volatile("bar.sync %0, %1;" :: "r"(grp + 1), "r"(GSZ) : "memory");
}
__device__ __forceinline__ void gwait(int grp, int gtid, unsigned target) {
    if (gtid == 0) {
        while (*(volatile unsigned*)&g_gen < target) {}
        __threadfence();
    }
    gsync(grp);
}

// ---------- chunk permutation: 16 chunks per group ----------
template <int CELL>
__device__ __forceinline__ int perm_ch(int i, int grp) {
    if (CELL == 0) return 2 * i + grp;
    return (i < 8) ? (16 + 2 * i + grp) : (2 * (i - 8) + grp);
}

// ---------- staged fragment load (256 threads per group) ----------
struct Frag { uint4 ah[4], al[4], bh, bl; };

template <int CELL>
__device__ __forceinline__ void load_frag(Frag& f, int ch, int t, int p, int n0, int gtid,
                                          const float* __restrict__ x) {
    const int k0 = ch * 64;
    {
        const __nv_bfloat16* Wh = CELL ? g_W1h : g_W0h;
        const __nv_bfloat16* Wl = CELL ? g_W1l : g_W0l;
        size_t wo = (size_t)(n0 + (gtid >> 3)) * 2048 + k0 + (gtid & 7) * 8;
        f.bh = __ldg((const uint4*)(Wh + wo));
        f.bl = __ldg((const uint4*)(Wl + wo));
    }
    if (CELL == 0 && ch < 16) {
#pragma unroll
        for (int it = 0; it < 4; it++) {
            int slot = it * GSZ + gtid;
            int b = slot >> 3, k = k0 + (slot & 7) * 8;
            const float* src = x + ((size_t)b * SS + t) * HH + k;
            float4 v0 = __ldg((const float4*)src);
            float4 v1 = __ldg((const float4*)(src + 4));
            cvt8(f.ah[it], f.al[it], v0, v1);
        }
    } else {
        const __nv_bfloat16 *sh, *sl;
        if (CELL == 0)      { sh = g_h0h[p];     sl = g_h0l[p]; }
        else if (ch < 16)   { sh = g_h0h[1 - p]; sl = g_h0l[1 - p]; }
        else                { sh = g_h1h[p];     sl = g_h1l[p]; }
        int kb = k0 & 1023;
#pragma unroll
        for (int it = 0; it < 4; it++) {
            int slot = it * GSZ + gtid;
            int b = slot >> 3, k = kb + (slot & 7) * 8;
            size_t o = (size_t)b * HH + k;
            f.ah[it] = __ldcg((const uint4*)(sh + o));
            f.al[it] = __ldcg((const uint4*)(sl + o));
        }
    }
}

__device__ __forceinline__ void sts_frag(char* stage, const Frag& f, int gtid) {
    int off = (gtid >> 3) * 128 + (gtid & 7) * 16;
    sts16(stage + 2 * STG_A, off, f.bh);
    sts16(stage + 2 * STG_A + STG_B, off, f.bl);
#pragma unroll
    for (int it = 0; it < 4; it++) {
        int slot = it * GSZ + gtid;
        int o2 = (slot >> 3) * 128 + (slot & 7) * 16;
        sts16(stage, o2, f.ah[it]);
        sts16(stage + STG_A, o2, f.al[it]);
    }
}

struct SmemT {
    float As[2][32][129];
    float bias[2][32];
    float sw8[8];
    float c0s[128][8], c1s[128][8];
    float h0s[128][8], h1s[128][8];
};

// ---------- GEMM: 2 groups x 8 warps; warp w -> rows 16w..+15, cols 0..31 ----------
template <int CELL>
__device__ __forceinline__ void run_gemm(SmemT& s, char* dyn, const float* __restrict__ x,
    int t, int p, int n0, int tid, float acc[4][4], u32 dynb, unsigned wA)
{
    const int grp = tid >> 8, gtid = tid & 255;
    const int lane = tid & 31, w = (tid >> 5) & 7;
    const int arow = 16 * w + (lane & 15);
    const int akhi = lane >> 4;
    const int brow = (lane & 7) + ((lane >> 4) << 3);
    const int bkhi = (lane >> 3) & 1;
    const u32 aoff = (u32)arow * 128;
    const int asw = arow & 7;
    const u32 boff = (u32)brow * 128;
    const int bsw = brow & 7;

    char* sb = dyn + grp * 2 * STG_STRIDE;
    const u32 gbase = dynb + (u32)(grp * 2 * STG_STRIDE);

    Frag f;
    load_frag<CELL>(f, perm_ch<CELL>(0, grp), t, p, n0, gtid, x);
    sts_frag(sb, f, gtid);
    load_frag<CELL>(f, perm_ch<CELL>(1, grp), t, p, n0, gtid, x);
    gsync(grp);

#pragma unroll 1
    for (int i = 0; i < 16; i++) {
        if (i < 15) sts_frag(sb + ((i + 1) & 1) * STG_STRIDE, f, gtid);
        if (CELL == 1 && i == 6) gwait(grp, gtid, wA);   // h0-dependent loads start at i=6
        if (i < 14) load_frag<CELL>(f, perm_ch<CELL>(i + 2, grp), t, p, n0, gtid, x);
        const u32 base = gbase + (u32)((i & 1) * STG_STRIDE);
        const u32 aAh = base + aoff;
        const u32 aAl = base + STG_A + aoff;
        const u32 aBh = base + 2 * STG_A + boff;
        const u32 aBl = base + 2 * STG_A + STG_B + boff;
#pragma unroll
        for (int ks = 0; ks < 4; ks++) {
            const u32 ao = (u32)(((2 * ks + akhi) ^ asw) << 4);
            const u32 bo = (u32)(((2 * ks + bkhi) ^ bsw) << 4);
            u32 ah[4], al[4], bh[8], bl[8];
            ldsm4(aAh + ao, ah[0], ah[1], ah[2], ah[3]);
            ldsm4(aAl + ao, al[0], al[1], al[2], al[3]);
            ldsm4(aBh + bo, bh[0], bh[1], bh[2], bh[3]);
            ldsm4(aBh + 16 * 128 + bo, bh[4], bh[5], bh[6], bh[7]);
            ldsm4(aBl + bo, bl[0], bl[1], bl[2], bl[3]);
            ldsm4(aBl + 16 * 128 + bo, bl[4], bl[5], bl[6], bl[7]);
            mma16816(acc[0], ah, bh[0], bh[1]);
            mma16816(acc[1], ah, bh[2], bh[3]);
            mma16816(acc[2], ah, bh[4], bh[5]);
            mma16816(acc[3], ah, bh[6], bh[7]);
            mma16816(acc[0], ah, bl[0], bl[1]);
            mma16816(acc[1], ah, bl[2], bl[3]);
            mma16816(acc[2], ah, bl[4], bl[5]);
            mma16816(acc[3], ah, bl[6], bl[7]);
            mma16816(acc[0], al, bh[0], bh[1]);
            mma16816(acc[1], al, bh[2], bh[3]);
            mma16816(acc[2], al, bh[4], bh[5]);
            mma16816(acc[3], al, bh[6], bh[7]);
        }
        gsync(grp);
    }
#pragma unroll
    for (int fr = 0; fr < 4; fr++) {
        int nn = fr * 8 + 2 * (lane & 3);
        int r = 16 * w + (lane >> 2);
        s.As[grp][nn][r]         = acc[fr][0];
        s.As[grp][nn + 1][r]     = acc[fr][1];
        s.As[grp][nn][r + 8]     = acc[fr][2];
        s.As[grp][nn + 1][r + 8] = acc[fr][3];
    }
    __syncthreads();
}

// ---------- main persistent kernel ----------
__global__ void __launch_bounds__(NT, 1) lstm_kernel(
    const float* __restrict__ x,
    const float* __restrict__ b0, const float* __restrict__ b1,
    const float* __restrict__ sw, const float* __restrict__ sb,
    float* __restrict__ out) {
    extern __shared__ __align__(1024) char dyn[];
    __shared__ SmemT s;

    const int tid = threadIdx.x, cb = blockIdx.x;
    const int j0 = cb * 8, n0 = cb * 32;

    if (tid < 64) {
        int layer = tid >> 5, c = tid & 31;
        const float* bp = layer ? b1 : b0;
        s.bias[layer][c] = bp[(c & 3) * 1024 + j0 + (c >> 2)];
    }
    if (tid < 8) s.sw8[tid] = sw[j0 + tid];
    if (tid < 128) {
#pragma unroll
        for (int jj = 0; jj < 8; jj++) {
            s.c0s[tid][jj] = 0.f; s.c1s[tid][jj] = 0.f;
            s.h0s[tid][jj] = 0.f; s.h1s[tid][jj] = 0.f;
        }
    }
    __syncthreads();

    const u32 dynb = smem_u32(dyn);

    float ut = 1.f;
    unsigned bt = 0, wA = 0, wB = 0;

#pragma unroll 1
    for (int t = 0; t < SS; t++) {
        const int p = t & 1;
        // ===== layer 0 GEMM =====
        {
            float acc[4][4] = {};
            run_gemm<0>(s, dyn, x, t, p, n0, tid, acc, dynb, 0u);
        }
        // ===== deferred skip-gate update for step t-1 (barrier B hidden under L0 GEMM) =====
        if (t > 0) {
            gbar_wait(wB);
            if (tid < 128) {
                float tot = sb[0];
                const float4* q = (const float4*)&g_sp[tid][0];
#pragma unroll
                for (int i = 0; i < 32; i++) {
                    float4 v = __ldcg(q + i);
                    tot += v.x + v.y + v.z + v.w;
                }
                float cum = sigf(tot);
                float u = rintf(ut);
                ut = (u > 0.5f) ? cum : (ut + fminf(cum, 1.f - ut));
            }
        }
        // ===== layer 0 epilogue =====
        if (tid < 128) {
            int b = tid;
            float u = rintf(ut);
#pragma unroll
            for (int jj = 0; jj < 8; jj++) {
                float ai = s.As[0][jj * 4 + 0][b] + s.As[1][jj * 4 + 0][b] + s.bias[0][jj * 4 + 0];
                float af = s.As[0][jj * 4 + 1][b] + s.As[1][jj * 4 + 1][b] + s.bias[0][jj * 4 + 1];
                float ag = s.As[0][jj * 4 + 2][b] + s.As[1][jj * 4 + 2][b] + s.bias[0][jj * 4 + 2];
                float ao = s.As[0][jj * 4 + 3][b] + s.As[1][jj * 4 + 3][b] + s.bias[0][jj * 4 + 3];
                float ig = sigf(ai);
                float fg = sigf(af);
                float gg = tanhfast(ag);
                float og = sigf(ao);
                float cn = fg * s.c0s[b][jj] + ig * gg;
                s.c0s[b][jj] = cn;
                float hn = u * (og * tanhfast(cn)) + (1.f - u) * s.h0s[b][jj];
                s.h0s[b][jj] = hn;
                __nv_bfloat16 hi = __float2bfloat16(hn);
                __stcg(&g_h0h[1 - p][(size_t)b * HH + j0 + jj], hi);
                __stcg(&g_h0l[1 - p][(size_t)b * HH + j0 + jj],
                       __float2bfloat16(hn - __bfloat162float(hi)));
            }
        }
        gbar_arrive(); wA = ++bt;
        // ===== layer 1 GEMM (h1 chunks first; group-scoped wait for barrier A) =====
        {
            float acc[4][4] = {};
            run_gemm<1>(s, dyn, x, t, p, n0, tid, acc, dynb, wA);
        }
        // ===== layer 1 epilogue =====
        if (tid < 128) {
            int b = tid;
            float u = rintf(ut);
            float sp = 0.f;
#pragma unroll
            for (int jj = 0; jj < 8; jj++) {
                float ai = s.As[0][jj * 4 + 0][b] + s.As[1][jj * 4 + 0][b] + s.bias[1][jj * 4 + 0];
                float af = s.As[0][jj * 4 + 1][b] + s.As[1][jj * 4 + 1][b] + s.bias[1][jj * 4 + 1];
                float ag = s.As[0][jj * 4 + 2][b] + s.As[1][jj * 4 + 2][b] + s.bias[1][jj * 4 + 2];
                float ao = s.As[0][jj * 4 + 3][b] + s.As[1][jj * 4 + 3][b] + s.bias[1][jj * 4 + 3];
                float ig = sigf(ai);
                float fg = sigf(af);
                float gg = tanhfast(ag);
                float og = sigf(ao);
                float cn = fg * s.c1s[b][jj] + ig * gg;
                s.c1s[b][jj] = cn;
                sp += cn * s.sw8[jj];
                float hn = u * (og * tanhfast(cn)) + (1.f - u) * s.h1s[b][jj];
                s.h1s[b][jj] = hn;
                __nv_bfloat16 hi = __float2bfloat16(hn);
                __stcg(&g_h1h[1 - p][(size_t)b * HH + j0 + jj], hi);
                __stcg(&g_h1l[1 - p][(size_t)b * HH + j0 + jj],
                       __float2bfloat16(hn - __bfloat162float(hi)));
                out[((size_t)b * SS + t) * HH + j0 + jj] = hn;
            }
            __stcg(&g_sp[b][cb], sp);
        }
        gbar_arrive(); wB = ++bt;
    }
}

extern "C" void kernel_launch(void* const* d_in, const int* in_sizes, int n_in,
                              void* d_out, int out_size) {
    (void)in_sizes; (void)n_in; (void)out_size;
    const float* x  = (const float*)d_in[0];
    const float* U0 = (const float*)d_in[1];
    const float* V0 = (const float*)d_in[2];
    const float* b0 = (const float*)d_in[3];
    const float* U1 = (const float*)d_in[4];
    const float* V1 = (const float*)d_in[5];
    const float* b1 = (const float*)d_in[6];
    const float* sw = (const float*)d_in[7];
    const float* sb = (const float*)d_in[8];
    float* out = (float*)d_out;

    cudaFuncSetAttribute(lstm_kernel, cudaFuncAttributeMaxDynamicSharedMemorySize, SMEM_DYN);
    conv_w<<<65536, 256>>>(U0, V0, U1, V1);
    lstm_kernel<<<NB, NT, SMEM_DYN>>>(x, b0, b1, sw, sb, out);
}

// round 12
// speedup vs baseline: 2.0474x; 2.0474x over previous
#include <cuda_runtime.h>
#include <cuda_bf16.h>
#include <cstdint>

typedef uint32_t u32; typedef uint64_t u64;

#define NB 128
#define NT 512
#define GSZ 256
#define SS 512
#define HH 1024
#define STG_A 16384
#define STG_B 4096
#define STG_STRIDE (2 * STG_A + 2 * STG_B)   // 40960
#define SMEM_DYN (4 * STG_STRIDE)            // 163840 (2 groups x 2 buffers)

// ---------- persistent device state ----------
__device__ __nv_bfloat16 g_W0h[8388608], g_W0l[8388608];   // [n'=j*4+g][k] (k contig, 2048)
__device__ __nv_bfloat16 g_W1h[8388608], g_W1l[8388608];
__device__ __nv_bfloat16 g_xh[67108864], g_xl[67108864];   // pre-split x (B,S,IN)
__device__ __nv_bfloat16 g_h0h[2][131072], g_h0l[2][131072];
__device__ __nv_bfloat16 g_h1h[2][131072], g_h1l[2][131072];
__device__ float g_sp[128][128];   // [b][cb]
__device__ unsigned g_cnt, g_gen;

// ---------- helpers ----------
__device__ __forceinline__ u32 smem_u32(const void* p) {
    u32 a; asm("{ .reg .u64 t; cvta.to.shared.u64 t, %1; cvt.u32.u64 %0, t; }" : "=r"(a) : "l"(p));
    return a;
}
__device__ __forceinline__ void ldsm4(u32 a, u32& r0, u32& r1, u32& r2, u32& r3) {
    asm volatile("ldmatrix.sync.aligned.m8n8.x4.shared.b16 {%0,%1,%2,%3}, [%4];"
        : "=r"(r0), "=r"(r1), "=r"(r2), "=r"(r3) : "r"(a));
}
__device__ __forceinline__ void mma16816(float* c, const u32* a, u32 b0, u32 b1) {
    asm volatile("mma.sync.aligned.m16n8k16.row.col.f32.bf16.bf16.f32 "
        "{%0,%1,%2,%3}, {%4,%5,%6,%7}, {%8,%9}, {%0,%1,%2,%3};"
        : "+f"(c[0]), "+f"(c[1]), "+f"(c[2]), "+f"(c[3])
        : "r"(a[0]), "r"(a[1]), "r"(a[2]), "r"(a[3]), "r"(b0), "r"(b1));
}
__device__ __forceinline__ void cpa16(u32 dst, const void* src) {
    asm volatile("cp.async.cg.shared.global [%0], [%1], 16;" :: "r"(dst), "l"(src));
}
#define CPA_COMMIT() asm volatile("cp.async.commit_group;" ::: "memory")
#define CPA_WAIT1()  asm volatile("cp.async.wait_group 1;" ::: "memory")
#define CPA_WAIT0()  asm volatile("cp.async.wait_group 0;" ::: "memory")

__device__ __forceinline__ u32 swz(u32 off) { return off ^ ((off >> 3) & 0x70); }
__device__ __forceinline__ float sigf(float x) {
    return __fdividef(1.f, 1.f + __expf(-x));
}
__device__ __forceinline__ float tanhfast(float x) {
    return 1.f - __fdividef(2.f, 1.f + __expf(2.f * x));
}

// ---------- init kernels ----------
__global__ void conv_w(const float* __restrict__ U0, const float* __restrict__ V0,
                       const float* __restrict__ U1, const float* __restrict__ V1) {
    size_t i = (size_t)blockIdx.x * 256 + threadIdx.x;   // 2 * 4096 * 2048
    if (i < 131072) {
        __nv_bfloat16 z = __float2bfloat16(0.f);
        g_h0h[0][i] = z; g_h0l[0][i] = z; g_h1h[0][i] = z; g_h1l[0][i] = z;
    }
    if (i == 0) { g_cnt = 0; g_gen = 0; }
    int layer = (int)(i >> 23);
    size_t r = i & 8388607;
    int np = (int)(r >> 11), k = (int)(r & 2047);
    int g = np & 3, j = np >> 2;
    const float* src = layer ? (k < 1024 ? U1 : V1) : (k < 1024 ? U0 : V0);
    float v = src[(size_t)(k & 1023) * 4096 + g * 1024 + j];
    __nv_bfloat16 hi = __float2bfloat16(v);
    __nv_bfloat16 lo = __float2bfloat16(v - __bfloat162float(hi));
    if (layer) { g_W1h[r] = hi; g_W1l[r] = lo; }
    else       { g_W0h[r] = hi; g_W0l[r] = lo; }
}
__global__ void conv_x(const float* __restrict__ x) {
    size_t i = (size_t)blockIdx.x * 256 + threadIdx.x;   // 128*512*1024
    float v = x[i];
    __nv_bfloat16 hi = __float2bfloat16(v);
    g_xh[i] = hi;
    g_xl[i] = __float2bfloat16(v - __bfloat162float(hi));
}

// ---------- barriers ----------
__device__ __forceinline__ void gbar_arrive() {
    __syncthreads();
    if (threadIdx.x == 0) {
        __threadfence();
        if (atomicAdd(&g_cnt, 1u) == NB - 1) {
            g_cnt = 0; __threadfence(); atomicAdd(&g_gen, 1u);
        }
    }
}
__device__ __forceinline__ void gbar_wait(unsigned target) {
    if (threadIdx.x == 0) {
        while (*(volatile unsigned*)&g_gen < target) {}
        __threadfence();
    }
    __syncthreads();
}
__device__ __forceinline__ void gsync(int grp) {
    asm volatile("bar.sync %0, %1;" :: "r"(grp + 1), "r"(GSZ) : "memory");
}
__device__ __forceinline__ void gwait(int grp, int gtid, unsigned target) {
    if (gtid == 0) {
        while (*(volatile unsigned*)&g_gen < target) {}
        __threadfence();
    }
    gsync(grp);
}

// ---------- chunk permutation: 16 chunks per group ----------
template <int CELL>
__device__ __forceinline__ int perm_ch(int i, int grp) {
    if (CELL == 0) return 2 * i + grp;
    return (i < 8) ? (16 + 2 * i + grp) : (2 * (i - 8) + grp);
}

// ---------- cp.async stage load (256 threads per group, no registers held) ----------
template <int CELL>
__device__ __forceinline__ void load_stage(u32 sb, int ch, int t, int p, int n0, int gtid) {
    const int k0 = ch * 64;
    {
        const __nv_bfloat16* Wh = CELL ? g_W1h : g_W0h;
        const __nv_bfloat16* Wl = CELL ? g_W1l : g_W0l;
        size_t wo = (size_t)(n0 + (gtid >> 3)) * 2048 + k0 + (gtid & 7) * 8;
        u32 off = swz((u32)((gtid >> 3) * 128 + (gtid & 7) * 16));
        cpa16(sb + 2 * STG_A + off, Wh + wo);
        cpa16(sb + 2 * STG_A + STG_B + off, Wl + wo);
    }
#pragma unroll
    for (int it = 0; it < 4; it++) {
        int slot = it * GSZ + gtid;
        int b = slot >> 3, kq = (slot & 7) * 8;
        u32 da = sb + swz((u32)((slot >> 3) * 128 + (slot & 7) * 16));
        const __nv_bfloat16 *ph, *pl;
        size_t go;
        if (CELL == 0 && ch < 16) {
            go = ((size_t)b * SS + t) * HH + k0 + kq;
            ph = g_xh; pl = g_xl;
        } else if (CELL == 0) {
            go = (size_t)b * HH + (k0 - 1024) + kq;
            ph = g_h0h[p]; pl = g_h0l[p];
        } else if (ch < 16) {
            go = (size_t)b * HH + k0 + kq;
            ph = g_h0h[1 - p]; pl = g_h0l[1 - p];
        } else {
            go = (size_t)b * HH + (k0 - 1024) + kq;
            ph = g_h1h[p]; pl = g_h1l[p];
        }
        cpa16(da, ph + go);
        cpa16(da + STG_A, pl + go);
    }
}

struct SmemT {
    float As[2][32][129];
    float bias[2][32];
    float sw8[8];
    float c0s[128][8], c1s[128][8];
    float h0s[128][8], h1s[128][8];
};

// ---------- GEMM: 2 groups x 8 warps; warp w -> rows 16w..+15, cols 0..31 ----------
template <int CELL>
__device__ __forceinline__ void run_gemm(SmemT& s, int t, int p, int n0, int tid,
                                         float acc[4][4], u32 dynb, unsigned wA)
{
    const int grp = tid >> 8, gtid = tid & 255;
    const int lane = tid & 31, w = (tid >> 5) & 7;
    const int arow = 16 * w + (lane & 15);
    const int akhi = lane >> 4;
    const int brow = (lane & 7) + ((lane >> 4) << 3);
    const int bkhi = (lane >> 3) & 1;
    const u32 aoff = (u32)arow * 128;
    const int asw = arow & 7;
    const u32 boff = (u32)brow * 128;
    const int bsw = brow & 7;

    const u32 gbase = dynb + (u32)(grp * 2 * STG_STRIDE);

    load_stage<CELL>(gbase, perm_ch<CELL>(0, grp), t, p, n0, gtid);
    CPA_COMMIT();
    load_stage<CELL>(gbase + STG_STRIDE, perm_ch<CELL>(1, grp), t, p, n0, gtid);
    CPA_COMMIT();

#pragma unroll 1
    for (int i = 0; i < 16; i++) {
        if (i >= 14) { CPA_WAIT0(); } else { CPA_WAIT1(); }
        gsync(grp);                      // stage i resident for whole group
        const u32 base = gbase + (u32)((i & 1) * STG_STRIDE);
        const u32 aAh = base + aoff;
        const u32 aAl = base + STG_A + aoff;
        const u32 aBh = base + 2 * STG_A + boff;
        const u32 aBl = base + 2 * STG_A + STG_B + boff;
#pragma unroll
        for (int ks = 0; ks < 4; ks++) {
            const u32 ao = (u32)(((2 * ks + akhi) ^ asw) << 4);
            const u32 bo = (u32)(((2 * ks + bkhi) ^ bsw) << 4);
            u32 ah[4], al[4], bh[8], bl[8];
            ldsm4(aAh + ao, ah[0], ah[1], ah[2], ah[3]);
            ldsm4(aAl + ao, al[0], al[1], al[2], al[3]);
            ldsm4(aBh + bo, bh[0], bh[1], bh[2], bh[3]);
            ldsm4(aBh + 16 * 128 + bo, bh[4], bh[5], bh[6], bh[7]);
            ldsm4(aBl + bo, bl[0], bl[1], bl[2], bl[3]);
            ldsm4(aBl + 16 * 128 + bo, bl[4], bl[5], bl[6], bl[7]);
            mma16816(acc[0], ah, bh[0], bh[1]);
            mma16816(acc[1], ah, bh[2], bh[3]);
            mma16816(acc[2], ah, bh[4], bh[5]);
            mma16816(acc[3], ah, bh[6], bh[7]);
            mma16816(acc[0], ah, bl[0], bl[1]);
            mma16816(acc[1], ah, bl[2], bl[3]);
            mma16816(acc[2], ah, bl[4], bl[5]);
            mma16816(acc[3], ah, bl[6], bl[7]);
            mma16816(acc[0], al, bh[0], bh[1]);
            mma16816(acc[1], al, bh[2], bh[3]);
            mma16816(acc[2], al, bh[4], bh[5]);
            mma16816(acc[3], al, bh[6], bh[7]);
        }
        gsync(grp);                      // all reads done before buffer reuse
        if (CELL == 1 && i == 6) gwait(grp, gtid, wA);   // before h0-dep loads (stage 8)
        if (i < 14) {
            load_stage<CELL>(gbase + (u32)((i & 1) * STG_STRIDE),
                             perm_ch<CELL>(i + 2, grp), t, p, n0, gtid);
            CPA_COMMIT();
        }
    }
#pragma unroll
    for (int fr = 0; fr < 4; fr++) {
        int nn = fr * 8 + 2 * (lane & 3);
        int r = 16 * w + (lane >> 2);
        s.As[grp][nn][r]         = acc[fr][0];
        s.As[grp][nn + 1][r]     = acc[fr][1];
        s.As[grp][nn][r + 8]     = acc[fr][2];
        s.As[grp][nn + 1][r + 8] = acc[fr][3];
    }
    __syncthreads();
}

// ---------- main persistent kernel ----------
__global__ void __launch_bounds__(NT, 1) lstm_kernel(
    const float* __restrict__ b0, const float* __restrict__ b1,
    const float* __restrict__ sw, const float* __restrict__ sb,
    float* __restrict__ out) {
    extern __shared__ __align__(1024) char dyn[];
    __shared__ SmemT s;

    const int tid = threadIdx.x, cb = blockIdx.x;
    const int j0 = cb * 8, n0 = cb * 32;

    if (tid < 64) {
        int layer = tid >> 5, c = tid & 31;
        const float* bp = layer ? b1 : b0;
        s.bias[layer][c] = bp[(c & 3) * 1024 + j0 + (c >> 2)];
    }
    if (tid < 8) s.sw8[tid] = sw[j0 + tid];
    if (tid < 128) {
#pragma unroll
        for (int jj = 0; jj < 8; jj++) {
            s.c0s[tid][jj] = 0.f; s.c1s[tid][jj] = 0.f;
            s.h0s[tid][jj] = 0.f; s.h1s[tid][jj] = 0.f;
        }
    }
    __syncthreads();

    const u32 dynb = smem_u32(dyn);

    float ut = 1.f;
    unsigned bt = 0, wA = 0, wB = 0;

#pragma unroll 1
    for (int t = 0; t < SS; t++) {
        const int p = t & 1;
        // ===== layer 0 GEMM =====
        {
            float acc[4][4] = {};
            run_gemm<0>(s, t, p, n0, tid, acc, dynb, 0u);
        }
        // ===== deferred skip-gate update for step t-1 (barrier B hidden under L0 GEMM) =====
        if (t > 0) {
            gbar_wait(wB);
            if (tid < 128) {
                float tot = sb[0];
                const float4* q = (const float4*)&g_sp[tid][0];
#pragma unroll
                for (int i = 0; i < 32; i++) {
                    float4 v = __ldcg(q + i);
                    tot += v.x + v.y + v.z + v.w;
                }
                float cum = sigf(tot);
                float u = rintf(ut);
                ut = (u > 0.5f) ? cum : (ut + fminf(cum, 1.f - ut));
            }
        }
        // ===== layer 0 epilogue =====
        if (tid < 128) {
            int b = tid;
            float u = rintf(ut);
#pragma unroll
            for (int jj = 0; jj < 8; jj++) {
                float ai = s.As[0][jj * 4 + 0][b] + s.As[1][jj * 4 + 0][b] + s.bias[0][jj * 4 + 0];
                float af = s.As[0][jj * 4 + 1][b] + s.As[1][jj * 4 + 1][b] + s.bias[0][jj * 4 + 1];
                float ag = s.As[0][jj * 4 + 2][b] + s.As[1][jj * 4 + 2][b] + s.bias[0][jj * 4 + 2];
                float ao = s.As[0][jj * 4 + 3][b] + s.As[1][jj * 4 + 3][b] + s.bias[0][jj * 4 + 3];
                float ig = sigf(ai);
                float fg = sigf(af);
                float gg = tanhfast(ag);
                float og = sigf(ao);
                float cn = fg * s.c0s[b][jj] + ig * gg;
                s.c0s[b][jj] = cn;
                float hn = u * (og * tanhfast(cn)) + (1.f - u) * s.h0s[b][jj];
                s.h0s[b][jj] = hn;
                __nv_bfloat16 hi = __float2bfloat16(hn);
                __stcg(&g_h0h[1 - p][(size_t)b * HH + j0 + jj], hi);
                __stcg(&g_h0l[1 - p][(size_t)b * HH + j0 + jj],
                       __float2bfloat16(hn - __bfloat162float(hi)));
            }
        }
        gbar_arrive(); wA = ++bt;
        // ===== layer 1 GEMM (h1 chunks first; group-scoped wait for barrier A) =====
        {
            float acc[4][4] = {};
            run_gemm<1>(s, t, p, n0, tid, acc, dynb, wA);
        }
        // ===== layer 1 epilogue =====
        if (tid < 128) {
            int b = tid;
            float u = rintf(ut);
            float sp = 0.f;
#pragma unroll
            for (int jj = 0; jj < 8; jj++) {
                float ai = s.As[0][jj * 4 + 0][b] + s.As[1][jj * 4 + 0][b] + s.bias[1][jj * 4 + 0];
                float af = s.As[0][jj * 4 + 1][b] + s.As[1][jj * 4 + 1][b] + s.bias[1][jj * 4 + 1];
                float ag = s.As[0][jj * 4 + 2][b] + s.As[1][jj * 4 + 2][b] + s.bias[1][jj * 4 + 2];
                float ao = s.As[0][jj * 4 + 3][b] + s.As[1][jj * 4 + 3][b] + s.bias[1][jj * 4 + 3];
                float ig = sigf(ai);
                float fg = sigf(af);
                float gg = tanhfast(ag);
                float og = sigf(ao);
                float cn = fg * s.c1s[b][jj] + ig * gg;
                s.c1s[b][jj] = cn;
                sp += cn * s.sw8[jj];
                float hn = u * (og * tanhfast(cn)) + (1.f - u) * s.h1s[b][jj];
                s.h1s[b][jj] = hn;
                __nv_bfloat16 hi = __float2bfloat16(hn);
                __stcg(&g_h1h[1 - p][(size_t)b * HH + j0 + jj], hi);
                __stcg(&g_h1l[1 - p][(size_t)b * HH + j0 + jj],
                       __float2bfloat16(hn - __bfloat162float(hi)));
                out[((size_t)b * SS + t) * HH + j0 + jj] = hn;
            }
            __stcg(&g_sp[b][cb], sp);
        }
        gbar_arrive(); wB = ++bt;
    }
}

extern "C" void kernel_launch(void* const* d_in, const int* in_sizes, int n_in,
                              void* d_out, int out_size) {
    (void)in_sizes; (void)n_in; (void)out_size;
    const float* x  = (const float*)d_in[0];
    const float* U0 = (const float*)d_in[1];
    const float* V0 = (const float*)d_in[2];
    const float* b0 = (const float*)d_in[3];
    const float* U1 = (const float*)d_in[4];
    const float* V1 = (const float*)d_in[5];
    const float* b1 = (const float*)d_in[6];
    const float* sw = (const float*)d_in[7];
    const float* sb = (const float*)d_in[8];
    float* out = (float*)d_out;

    cudaFuncSetAttribute(lstm_kernel, cudaFuncAttributeMaxDynamicSharedMemorySize, SMEM_DYN);
    conv_w<<<65536, 256>>>(U0, V0, U1, V1);
    conv_x<<<262144, 256>>>(x);
    lstm_kernel<<<NB, NT, SMEM_DYN>>>(b0, b1, sw, sb, out);
}

// round 13
// speedup vs baseline: 2.1100x; 1.0306x over previous
#include <cuda_runtime.h>
#include <cuda_fp16.h>
#include <cstdint>

typedef uint32_t u32; typedef uint64_t u64;

#define NB 128
#define NT 512
#define GSZ 256
#define SS 512
#define HH 1024
#define STG_A 16384
#define STG_B 4096
#define STG_STRIDE (2 * STG_A + 2 * STG_B)   // 40960
#define SMEM_DYN (4 * STG_STRIDE)            // 163840 (2 groups x 2 buffers)

// ---------- persistent device state (fp16 hi/lo splits) ----------
__device__ __half g_W0h[8388608], g_W0l[8388608];   // [n'=j*4+g][k] (k contig, 2048)
__device__ __half g_W1h[8388608], g_W1l[8388608];
__device__ __half g_xh[67108864], g_xl[67108864];   // pre-split x (B,S,IN)
__device__ __half g_h0h[2][131072], g_h0l[2][131072];
__device__ __half g_h1h[2][131072], g_h1l[2][131072];
__device__ float g_sp[128][128];   // [b][cb]
__device__ unsigned g_cnt, g_gen;

// ---------- helpers ----------
__device__ __forceinline__ u32 smem_u32(const void* p) {
    u32 a; asm("{ .reg .u64 t; cvta.to.shared.u64 t, %1; cvt.u32.u64 %0, t; }" : "=r"(a) : "l"(p));
    return a;
}
__device__ __forceinline__ void ldsm4(u32 a, u32& r0, u32& r1, u32& r2, u32& r3) {
    asm volatile("ldmatrix.sync.aligned.m8n8.x4.shared.b16 {%0,%1,%2,%3}, [%4];"
        : "=r"(r0), "=r"(r1), "=r"(r2), "=r"(r3) : "r"(a));
}
__device__ __forceinline__ void mma_f32(float* c, const u32* a, u32 b0, u32 b1) {
    asm volatile("mma.sync.aligned.m16n8k16.row.col.f32.f16.f16.f32 "
        "{%0,%1,%2,%3}, {%4,%5,%6,%7}, {%8,%9}, {%0,%1,%2,%3};"
        : "+f"(c[0]), "+f"(c[1]), "+f"(c[2]), "+f"(c[3])
        : "r"(a[0]), "r"(a[1]), "r"(a[2]), "r"(a[3]), "r"(b0), "r"(b1));
}
__device__ __forceinline__ void mma_f16(u32* c, const u32* a, u32 b0, u32 b1) {
    asm volatile("mma.sync.aligned.m16n8k16.row.col.f16.f16.f16.f16 "
        "{%0,%1}, {%2,%3,%4,%5}, {%6,%7}, {%0,%1};"
        : "+r"(c[0]), "+r"(c[1])
        : "r"(a[0]), "r"(a[1]), "r"(a[2]), "r"(a[3]), "r"(b0), "r"(b1));
}
__device__ __forceinline__ void cpa16(u32 dst, const void* src) {
    asm volatile("cp.async.cg.shared.global [%0], [%1], 16;" :: "r"(dst), "l"(src));
}
#define CPA_COMMIT() asm volatile("cp.async.commit_group;" ::: "memory")
#define CPA_WAIT1()  asm volatile("cp.async.wait_group 1;" ::: "memory")
#define CPA_WAIT0()  asm volatile("cp.async.wait_group 0;" ::: "memory")

__device__ __forceinline__ u32 swz(u32 off) { return off ^ ((off >> 3) & 0x70); }
__device__ __forceinline__ float sigf(float x) {
    return __fdividef(1.f, 1.f + __expf(-x));
}
__device__ __forceinline__ float tanhfast(float x) {
    return 1.f - __fdividef(2.f, 1.f + __expf(2.f * x));
}

// ---------- init kernels ----------
__global__ void conv_w(const float* __restrict__ U0, const float* __restrict__ V0,
                       const float* __restrict__ U1, const float* __restrict__ V1) {
    size_t i = (size_t)blockIdx.x * 256 + threadIdx.x;   // 2 * 4096 * 2048
    if (i < 131072) {
        __half z = __float2half(0.f);
        g_h0h[0][i] = z; g_h0l[0][i] = z; g_h1h[0][i] = z; g_h1l[0][i] = z;
    }
    if (i == 0) { g_cnt = 0; g_gen = 0; }
    int layer = (int)(i >> 23);
    size_t r = i & 8388607;
    int np = (int)(r >> 11), k = (int)(r & 2047);
    int g = np & 3, j = np >> 2;
    const float* src = layer ? (k < 1024 ? U1 : V1) : (k < 1024 ? U0 : V0);
    float v = src[(size_t)(k & 1023) * 4096 + g * 1024 + j];
    __half hi = __float2half(v);
    __half lo = __float2half(v - __half2float(hi));
    if (layer) { g_W1h[r] = hi; g_W1l[r] = lo; }
    else       { g_W0h[r] = hi; g_W0l[r] = lo; }
}
__global__ void conv_x(const float* __restrict__ x) {
    size_t i = (size_t)blockIdx.x * 256 + threadIdx.x;   // 128*512*1024
    float v = x[i];
    __half hi = __float2half(v);
    g_xh[i] = hi;
    g_xl[i] = __float2half(v - __half2float(hi));
}

// ---------- barriers ----------
__device__ __forceinline__ void gbar_arrive() {
    __syncthreads();
    if (threadIdx.x == 0) {
        __threadfence();
        if (atomicAdd(&g_cnt, 1u) == NB - 1) {
            g_cnt = 0; __threadfence(); atomicAdd(&g_gen, 1u);
        }
    }
}
__device__ __forceinline__ void gbar_wait(unsigned target) {
    if (threadIdx.x == 0) {
        while (*(volatile unsigned*)&g_gen < target) {}
        __threadfence();
    }
    __syncthreads();
}
__device__ __forceinline__ void gsync(int grp) {
    asm volatile("bar.sync %0, %1;" :: "r"(grp + 1), "r"(GSZ) : "memory");
}
__device__ __forceinline__ void gwait(int grp, int gtid, unsigned target) {
    if (gtid == 0) {
        while (*(volatile unsigned*)&g_gen < target) {}
        __threadfence();
    }
    gsync(grp);
}

// ---------- chunk permutation: 16 chunks per group ----------
template <int CELL>
__device__ __forceinline__ int perm_ch(int i, int grp) {
    if (CELL == 0) return 2 * i + grp;
    return (i < 8) ? (16 + 2 * i + grp) : (2 * (i - 8) + grp);
}

// ---------- cp.async stage load (256 threads per group) ----------
template <int CELL>
__device__ __forceinline__ void load_stage(u32 sb, int ch, int t, int p, int n0, int gtid) {
    const int k0 = ch * 64;
    {
        const __half* Wh = CELL ? g_W1h : g_W0h;
        const __half* Wl = CELL ? g_W1l : g_W0l;
        size_t wo = (size_t)(n0 + (gtid >> 3)) * 2048 + k0 + (gtid & 7) * 8;
        u32 off = swz((u32)((gtid >> 3) * 128 + (gtid & 7) * 16));
        cpa16(sb + 2 * STG_A + off, Wh + wo);
        cpa16(sb + 2 * STG_A + STG_B + off, Wl + wo);
    }
#pragma unroll
    for (int it = 0; it < 4; it++) {
        int slot = it * GSZ + gtid;
        int b = slot >> 3, kq = (slot & 7) * 8;
        u32 da = sb + swz((u32)((slot >> 3) * 128 + (slot & 7) * 16));
        const __half *ph, *pl;
        size_t go;
        if (CELL == 0 && ch < 16) {
            go = ((size_t)b * SS + t) * HH + k0 + kq;
            ph = g_xh; pl = g_xl;
        } else if (CELL == 0) {
            go = (size_t)b * HH + (k0 - 1024) + kq;
            ph = g_h0h[p]; pl = g_h0l[p];
        } else if (ch < 16) {
            go = (size_t)b * HH + k0 + kq;
            ph = g_h0h[1 - p]; pl = g_h0l[1 - p];
        } else {
            go = (size_t)b * HH + (k0 - 1024) + kq;
            ph = g_h1h[p]; pl = g_h1l[p];
        }
        cpa16(da, ph + go);
        cpa16(da + STG_A, pl + go);
    }
}

struct SmemT {
    float As[2][32][129];
    float bias[2][32];
    float sw8[8];
    float c0s[128][8], c1s[128][8];
    float h0s[128][8], h1s[128][8];
};

// ---------- GEMM: 2 groups x 8 warps; warp w -> rows 16w..+15, cols 0..31 ----------
template <int CELL>
__device__ __forceinline__ void run_gemm(SmemT& s, int t, int p, int n0, int tid,
                                         float acc[4][4], u32 corr[4][2],
                                         u32 dynb, unsigned wA)
{
    const int grp = tid >> 8, gtid = tid & 255;
    const int lane = tid & 31, w = (tid >> 5) & 7;
    const int arow = 16 * w + (lane & 15);
    const int akhi = lane >> 4;
    const int brow = (lane & 7) + ((lane >> 4) << 3);
    const int bkhi = (lane >> 3) & 1;
    const u32 aoff = (u32)arow * 128;
    const int asw = arow & 7;
    const u32 boff = (u32)brow * 128;
    const int bsw = brow & 7;

    const u32 gbase = dynb + (u32)(grp * 2 * STG_STRIDE);

    load_stage<CELL>(gbase, perm_ch<CELL>(0, grp), t, p, n0, gtid);
    CPA_COMMIT();
    load_stage<CELL>(gbase + STG_STRIDE, perm_ch<CELL>(1, grp), t, p, n0, gtid);
    CPA_COMMIT();

#pragma unroll 1
    for (int i = 0; i < 16; i++) {
        if (i >= 14) { CPA_WAIT0(); } else { CPA_WAIT1(); }
        gsync(grp);                      // stage i resident for whole group
        const u32 base = gbase + (u32)((i & 1) * STG_STRIDE);
        const u32 aAh = base + aoff;
        const u32 aAl = base + STG_A + aoff;
        const u32 aBh = base + 2 * STG_A + boff;
        const u32 aBl = base + 2 * STG_A + STG_B + boff;
#pragma unroll
        for (int ks = 0; ks < 4; ks++) {
            const u32 ao = (u32)(((2 * ks + akhi) ^ asw) << 4);
            const u32 bo = (u32)(((2 * ks + bkhi) ^ bsw) << 4);
            u32 ah[4], al[4], bh[8], bl[8];
            ldsm4(aAh + ao, ah[0], ah[1], ah[2], ah[3]);
            ldsm4(aAl + ao, al[0], al[1], al[2], al[3]);
            ldsm4(aBh + bo, bh[0], bh[1], bh[2], bh[3]);
            ldsm4(aBh + 16 * 128 + bo, bh[4], bh[5], bh[6], bh[7]);
            ldsm4(aBl + bo, bl[0], bl[1], bl[2], bl[3]);
            ldsm4(aBl + 16 * 128 + bo, bl[4], bl[5], bl[6], bl[7]);
            // main product (fp32 accumulate, full rate)
            mma_f32(acc[0], ah, bh[0], bh[1]);
            mma_f32(acc[1], ah, bh[2], bh[3]);
            mma_f32(acc[2], ah, bh[4], bh[5]);
            mma_f32(acc[3], ah, bh[6], bh[7]);
            // corrections (fp16 accumulate, 2x rate, shared accumulator)
            mma_f16(corr[0], ah, bl[0], bl[1]);
            mma_f16(corr[1], ah, bl[2], bl[3]);
            mma_f16(corr[2], ah, bl[4], bl[5]);
            mma_f16(corr[3], ah, bl[6], bl[7]);
            mma_f16(corr[0], al, bh[0], bh[1]);
            mma_f16(corr[1], al, bh[2], bh[3]);
            mma_f16(corr[2], al, bh[4], bh[5]);
            mma_f16(corr[3], al, bh[6], bh[7]);
        }
        gsync(grp);                      // all reads done before buffer reuse
        if (CELL == 1 && i == 6) gwait(grp, gtid, wA);   // before h0-dep loads (stage 8)
        if (i < 14) {
            load_stage<CELL>(gbase + (u32)((i & 1) * STG_STRIDE),
                             perm_ch<CELL>(i + 2, grp), t, p, n0, gtid);
            CPA_COMMIT();
        }
    }
#pragma unroll
    for (int fr = 0; fr < 4; fr++) {
        int nn = fr * 8 + 2 * (lane & 3);
        int r = 16 * w + (lane >> 2);
        float2 c01 = __half22float2(*(half2*)&corr[fr][0]);
        float2 c23 = __half22float2(*(half2*)&corr[fr][1]);
        s.As[grp][nn][r]         = acc[fr][0] + c01.x;
        s.As[grp][nn + 1][r]     = acc[fr][1] + c01.y;
        s.As[grp][nn][r + 8]     = acc[fr][2] + c23.x;
        s.As[grp][nn + 1][r + 8] = acc[fr][3] + c23.y;
    }
    __syncthreads();
}

// ---------- main persistent kernel ----------
__global__ void __launch_bounds__(NT, 1) lstm_kernel(
    const float* __restrict__ b0, const float* __restrict__ b1,
    const float* __restrict__ sw, const float* __restrict__ sb,
    float* __restrict__ out) {
    extern __shared__ __align__(1024) char dyn[];
    __shared__ SmemT s;

    const int tid = threadIdx.x, cb = blockIdx.x;
    const int j0 = cb * 8, n0 = cb * 32;

    if (tid < 64) {
        int layer = tid >> 5, c = tid & 31;
        const float* bp = layer ? b1 : b0;
        s.bias[layer][c] = bp[(c & 3) * 1024 + j0 + (c >> 2)];
    }
    if (tid < 8) s.sw8[tid] = sw[j0 + tid];
    if (tid < 128) {
#pragma unroll
        for (int jj = 0; jj < 8; jj++) {
            s.c0s[tid][jj] = 0.f; s.c1s[tid][jj] = 0.f;
            s.h0s[tid][jj] = 0.f; s.h1s[tid][jj] = 0.f;
        }
    }
    __syncthreads();

    const u32 dynb = smem_u32(dyn);

    float ut = 1.f;
    unsigned bt = 0, wA = 0, wB = 0;

#pragma unroll 1
    for (int t = 0; t < SS; t++) {
        const int p = t & 1;
        // ===== layer 0 GEMM =====
        {
            float acc[4][4] = {};
            u32 corr[4][2] = {};
            run_gemm<0>(s, t, p, n0, tid, acc, corr, dynb, 0u);
        }
        // ===== deferred skip-gate update for step t-1 (barrier B hidden under L0 GEMM) =====
        if (t > 0) {
            gbar_wait(wB);
            if (tid < 128) {
                float tot = sb[0];
                const float4* q = (const float4*)&g_sp[tid][0];
#pragma unroll
                for (int i = 0; i < 32; i++) {
                    float4 v = __ldcg(q + i);
                    tot += v.x + v.y + v.z + v.w;
                }
                float cum = sigf(tot);
                float u = rintf(ut);
                ut = (u > 0.5f) ? cum : (ut + fminf(cum, 1.f - ut));
            }
        }
        // ===== layer 0 epilogue =====
        if (tid < 128) {
            int b = tid;
            float u = rintf(ut);
#pragma unroll
            for (int jj = 0; jj < 8; jj++) {
                float ai = s.As[0][jj * 4 + 0][b] + s.As[1][jj * 4 + 0][b] + s.bias[0][jj * 4 + 0];
                float af = s.As[0][jj * 4 + 1][b] + s.As[1][jj * 4 + 1][b] + s.bias[0][jj * 4 + 1];
                float ag = s.As[0][jj * 4 + 2][b] + s.As[1][jj * 4 + 2][b] + s.bias[0][jj * 4 + 2];
                float ao = s.As[0][jj * 4 + 3][b] + s.As[1][jj * 4 + 3][b] + s.bias[0][jj * 4 + 3];
                float ig = sigf(ai);
                float fg = sigf(af);
                float gg = tanhfast(ag);
                float og = sigf(ao);
                float cn = fg * s.c0s[b][jj] + ig * gg;
                s.c0s[b][jj] = cn;
                float hn = u * (og * tanhfast(cn)) + (1.f - u) * s.h0s[b][jj];
                s.h0s[b][jj] = hn;
                __half hi = __float2half(hn);
                __stcg(&g_h0h[1 - p][(size_t)b * HH + j0 + jj], hi);
                __stcg(&g_h0l[1 - p][(size_t)b * HH + j0 + jj],
                       __float2half(hn - __half2float(hi)));
            }
        }
        gbar_arrive(); wA = ++bt;
        // ===== layer 1 GEMM (h1 chunks first; group-scoped wait for barrier A) =====
        {
            float acc[4][4] = {};
            u32 corr[4][2] = {};
            run_gemm<1>(s, t, p, n0, tid, acc, corr, dynb, wA);
        }
        // ===== layer 1 epilogue =====
        if (tid < 128) {
            int b = tid;
            float u = rintf(ut);
            float sp = 0.f;
#pragma unroll
            for (int jj = 0; jj < 8; jj++) {
                float ai = s.As[0][jj * 4 + 0][b] + s.As[1][jj * 4 + 0][b] + s.bias[1][jj * 4 + 0];
                float af = s.As[0][jj * 4 + 1][b] + s.As[1][jj * 4 + 1][b] + s.bias[1][jj * 4 + 1];
                float ag = s.As[0][jj * 4 + 2][b] + s.As[1][jj * 4 + 2][b] + s.bias[1][jj * 4 + 2];
                float ao = s.As[0][jj * 4 + 3][b] + s.As[1][jj * 4 + 3][b] + s.bias[1][jj * 4 + 3];
                float ig = sigf(ai);
                float fg = sigf(af);
                float gg = tanhfast(ag);
                float og = sigf(ao);
                float cn = fg * s.c1s[b][jj] + ig * gg;
                s.c1s[b][jj] = cn;
                sp += cn * s.sw8[jj];
                float hn = u * (og * tanhfast(cn)) + (1.f - u) * s.h1s[b][jj];
                s.h1s[b][jj] = hn;
                __half hi = __float2half(hn);
                __stcg(&g_h1h[1 - p][(size_t)b * HH + j0 + jj], hi);
                __stcg(&g_h1l[1 - p][(size_t)b * HH + j0 + jj],
                       __float2half(hn - __half2float(hi)));
                out[((size_t)b * SS + t) * HH + j0 + jj] = hn;
            }
            __stcg(&g_sp[b][cb], sp);
        }
        gbar_arrive(); wB = ++bt;
    }
}

extern "C" void kernel_launch(void* const* d_in, const int* in_sizes, int n_in,
                              void* d_out, int out_size) {
    (void)in_sizes; (void)n_in; (void)out_size;
    const float* x  = (const float*)d_in[0];
    const float* U0 = (const float*)d_in[1];
    const float* V0 = (const float*)d_in[2];
    const float* b0 = (const float*)d_in[3];
    const float* U1 = (const float*)d_in[4];
    const float* V1 = (const float*)d_in[5];
    const float* b1 = (const float*)d_in[6];
    const float* sw = (const float*)d_in[7];
    const float* sb = (const float*)d_in[8];
    float* out = (float*)d_out;

    cudaFuncSetAttribute(lstm_kernel, cudaFuncAttributeMaxDynamicSharedMemorySize, SMEM_DYN);
    conv_w<<<65536, 256>>>(U0, V0, U1, V1);
    conv_x<<<262144, 256>>>(x);
    lstm_kernel<<<NB, NT, SMEM_DYN>>>(b0, b1, sw, sb, out);
}

// round 14
// speedup vs baseline: 2.1921x; 1.0389x over previous
#include <cuda_runtime.h>
#include <cuda_fp16.h>
#include <cstdint>

typedef uint32_t u32; typedef uint64_t u64;

#define NB 128
#define NT 512
#define GSZ 256
#define SS 512
#define HH 1024
#define A_SLOT 32768               // Ah 16K + Al 16K
#define B_SLOT 8192                // Bh 4K + Bl 4K
#define B_BASE (2 * A_SLOT)        // 65536
#define GRP_STRIDE (2 * A_SLOT + 3 * B_SLOT)   // 90112
#define SMEM_DYN (2 * GRP_STRIDE)              // 180224

// ---------- persistent device state (fp16 hi/lo splits) ----------
__device__ __half g_W0h[8388608], g_W0l[8388608];   // [n'=j*4+g][k] (k contig, 2048)
__device__ __half g_W1h[8388608], g_W1l[8388608];
__device__ __half g_xh[67108864], g_xl[67108864];   // pre-split x (B,S,IN)
__device__ __half g_h0h[2][131072], g_h0l[2][131072];
__device__ __half g_h1h[2][131072], g_h1l[2][131072];
__device__ float g_sp[128][128];   // [b][cb]
__device__ unsigned g_cnt, g_gen;

// ---------- helpers ----------
__device__ __forceinline__ u32 smem_u32(const void* p) {
    u32 a; asm("{ .reg .u64 t; cvta.to.shared.u64 t, %1; cvt.u32.u64 %0, t; }" : "=r"(a) : "l"(p));
    return a;
}
__device__ __forceinline__ void ldsm4(u32 a, u32& r0, u32& r1, u32& r2, u32& r3) {
    asm volatile("ldmatrix.sync.aligned.m8n8.x4.shared.b16 {%0,%1,%2,%3}, [%4];"
        : "=r"(r0), "=r"(r1), "=r"(r2), "=r"(r3) : "r"(a));
}
__device__ __forceinline__ void mma_f32(float* c, const u32* a, u32 b0, u32 b1) {
    asm volatile("mma.sync.aligned.m16n8k16.row.col.f32.f16.f16.f32 "
        "{%0,%1,%2,%3}, {%4,%5,%6,%7}, {%8,%9}, {%0,%1,%2,%3};"
        : "+f"(c[0]), "+f"(c[1]), "+f"(c[2]), "+f"(c[3])
        : "r"(a[0]), "r"(a[1]), "r"(a[2]), "r"(a[3]), "r"(b0), "r"(b1));
}
__device__ __forceinline__ void mma_f16(u32* c, const u32* a, u32 b0, u32 b1) {
    asm volatile("mma.sync.aligned.m16n8k16.row.col.f16.f16.f16.f16 "
        "{%0,%1}, {%2,%3,%4,%5}, {%6,%7}, {%0,%1};"
        : "+r"(c[0]), "+r"(c[1])
        : "r"(a[0]), "r"(a[1]), "r"(a[2]), "r"(a[3]), "r"(b0), "r"(b1));
}
__device__ __forceinline__ void cpa16(u32 dst, const void* src) {
    asm volatile("cp.async.cg.shared.global [%0], [%1], 16;" :: "r"(dst), "l"(src));
}
#define CPA_COMMIT() asm volatile("cp.async.commit_group;" ::: "memory")
#define CPA_WAIT2()  asm volatile("cp.async.wait_group 2;" ::: "memory")
#define CPA_WAIT1()  asm volatile("cp.async.wait_group 1;" ::: "memory")
#define CPA_WAIT0()  asm volatile("cp.async.wait_group 0;" ::: "memory")

__device__ __forceinline__ u32 swz(u32 off) { return off ^ ((off >> 3) & 0x70); }
__device__ __forceinline__ float sigf(float x) {
    return __fdividef(1.f, 1.f + __expf(-x));
}
__device__ __forceinline__ float tanhfast(float x) {
    return 1.f - __fdividef(2.f, 1.f + __expf(2.f * x));
}

// ---------- merged init kernel (2 launches per replay -> lstm profiled) ----------
__global__ void conv_all(const float* __restrict__ U0, const float* __restrict__ V0,
                         const float* __restrict__ U1, const float* __restrict__ V1,
                         const float* __restrict__ x) {
    size_t i = (size_t)blockIdx.x * 256 + threadIdx.x;
    if (i < 16777216) {          // weights: 2 * 4096 * 2048
        if (i < 131072) {
            __half z = __float2half(0.f);
            g_h0h[0][i] = z; g_h0l[0][i] = z; g_h1h[0][i] = z; g_h1l[0][i] = z;
        }
        if (i == 0) { g_cnt = 0; g_gen = 0; }
        int layer = (int)(i >> 23);
        size_t r = i & 8388607;
        int np = (int)(r >> 11), k = (int)(r & 2047);
        int g = np & 3, j = np >> 2;
        const float* src = layer ? (k < 1024 ? U1 : V1) : (k < 1024 ? U0 : V0);
        float v = src[(size_t)(k & 1023) * 4096 + g * 1024 + j];
        __half hi = __float2half(v);
        __half lo = __float2half(v - __half2float(hi));
        if (layer) { g_W1h[r] = hi; g_W1l[r] = lo; }
        else       { g_W0h[r] = hi; g_W0l[r] = lo; }
    } else {                     // x: 128*512*1024
        size_t xi = i - 16777216;
        float v = x[xi];
        __half hi = __float2half(v);
        g_xh[xi] = hi;
        g_xl[xi] = __float2half(v - __half2float(hi));
    }
}

// ---------- barriers ----------
__device__ __forceinline__ void gbar_arrive() {
    __syncthreads();
    if (threadIdx.x == 0) {
        __threadfence();
        if (atomicAdd(&g_cnt, 1u) == NB - 1) {
            g_cnt = 0; __threadfence(); atomicAdd(&g_gen, 1u);
        }
    }
}
__device__ __forceinline__ void gbar_wait(unsigned target) {
    if (threadIdx.x == 0) {
        while (*(volatile unsigned*)&g_gen < target) {}
        __threadfence();
    }
    __syncthreads();
}
__device__ __forceinline__ void gsync(int grp) {
    asm volatile("bar.sync %0, %1;" :: "r"(grp + 1), "r"(GSZ) : "memory");
}
__device__ __forceinline__ void gwait(int grp, int gtid, unsigned target) {
    if (gtid == 0) {
        while (*(volatile unsigned*)&g_gen < target) {}
        __threadfence();
    }
    gsync(grp);
}

// ---------- chunk permutation: 16 chunks per group ----------
template <int CELL>
__device__ __forceinline__ int perm_ch(int i, int grp) {
    if (CELL == 0) return 2 * i + grp;
    return (i < 8) ? (16 + 2 * i + grp) : (2 * (i - 8) + grp);
}

// ---------- staging: B by whole group (3 rotating slots) ----------
template <int CELL>
__device__ __forceinline__ void stage_B(u32 gbase, int slot, int ch, int n0, int gtid) {
    const int k0 = ch * 64;
    const __half* Wh = CELL ? g_W1h : g_W0h;
    const __half* Wl = CELL ? g_W1l : g_W0l;
    size_t wo = (size_t)(n0 + (gtid >> 3)) * 2048 + k0 + (gtid & 7) * 8;
    u32 sb = gbase + B_BASE + (u32)slot * B_SLOT;
    u32 off = swz((u32)((gtid >> 3) * 128 + (gtid & 7) * 16));
    cpa16(sb + off, Wh + wo);
    cpa16(sb + 4096 + off, Wl + wo);
}

// ---------- staging: A rows warp-locally (each warp stages only rows it reads) ----------
template <int CELL>
__device__ __forceinline__ void stage_A(u32 gbase, int abuf, int ch, int t, int p,
                                        int w, int lane) {
    const int k0 = ch * 64;
    u32 sa = gbase + (u32)abuf * A_SLOT;
#pragma unroll
    for (int q = 0; q < 4; q++) {
        int idx = q * 32 + lane;            // 0..127 = 16 rows x 8 segs
        int b = 16 * w + (idx >> 3);
        int kq = (idx & 7) * 8;
        u32 off = swz((u32)(b * 128 + (idx & 7) * 16));
        const __half *ph, *pl;
        size_t go;
        if (CELL == 0 && ch < 16) {
            go = ((size_t)b * SS + t) * HH + k0 + kq;
            ph = g_xh; pl = g_xl;
        } else if (CELL == 0) {
            go = (size_t)b * HH + (k0 - 1024) + kq;
            ph = g_h0h[p]; pl = g_h0l[p];
        } else if (ch < 16) {
            go = (size_t)b * HH + k0 + kq;
            ph = g_h0h[1 - p]; pl = g_h0l[1 - p];
        } else {
            go = (size_t)b * HH + (k0 - 1024) + kq;
            ph = g_h1h[p]; pl = g_h1l[p];
        }
        cpa16(sa + off, ph + go);
        cpa16(sa + 16384 + off, pl + go);
    }
}

struct SmemT {
    float As[2][32][129];
    float bias[2][32];
    float sw8[8];
    float c0s[128][8], c1s[128][8];
    float h0s[128][8], h1s[128][8];
};

// ---------- GEMM: 2 groups x 8 warps; warp w -> rows 16w..+15, cols 0..31 ----------
template <int CELL>
__device__ __forceinline__ void run_gemm(SmemT& s, int t, int p, int n0, int tid,
                                         float acc[4][4], u32 corr[4][2],
                                         u32 dynb, unsigned wA)
{
    const int grp = tid >> 8, gtid = tid & 255;
    const int lane = tid & 31, w = (tid >> 5) & 7;
    const int arow = 16 * w + (lane & 15);
    const int akhi = lane >> 4;
    const int brow = (lane & 7) + ((lane >> 4) << 3);
    const int bkhi = (lane >> 3) & 1;
    const u32 aoff = (u32)arow * 128;
    const int asw = arow & 7;
    const u32 boff = (u32)brow * 128;
    const int bsw = brow & 7;

    const u32 gbase = dynb + (u32)(grp * GRP_STRIDE);

    stage_B<CELL>(gbase, 0, perm_ch<CELL>(0, grp), n0, gtid);
    stage_A<CELL>(gbase, 0, perm_ch<CELL>(0, grp), t, p, w, lane);
    CPA_COMMIT();
    stage_B<CELL>(gbase, 1, perm_ch<CELL>(1, grp), n0, gtid);
    stage_A<CELL>(gbase, 1, perm_ch<CELL>(1, grp), t, p, w, lane);
    CPA_COMMIT();

#pragma unroll 1
    for (int i = 0; i < 16; i++) {
        if (i == 0)      { CPA_WAIT1(); }
        else if (i < 15) { CPA_WAIT2(); }
        else             { CPA_WAIT0(); }
        gsync(grp);      // single barrier per chunk: stage i resident + prev reads done
        if (i < 14) {    // B for chunk i+2 (weights: never state-dependent)
            stage_B<CELL>(gbase, (i + 2) % 3, perm_ch<CELL>(i + 2, grp), n0, gtid);
            CPA_COMMIT();
        }
        const u32 aAh = gbase + (u32)((i & 1) * A_SLOT) + aoff;
        const u32 aAl = aAh + 16384;
        const u32 aBh = gbase + B_BASE + (u32)((i % 3) * B_SLOT) + boff;
        const u32 aBl = aBh + 4096;
#pragma unroll
        for (int ks = 0; ks < 4; ks++) {
            const u32 ao = (u32)(((2 * ks + akhi) ^ asw) << 4);
            const u32 bo = (u32)(((2 * ks + bkhi) ^ bsw) << 4);
            u32 ah[4], al[4], bh[8], bl[8];
            ldsm4(aAh + ao, ah[0], ah[1], ah[2], ah[3]);
            ldsm4(aAl + ao, al[0], al[1], al[2], al[3]);
            ldsm4(aBh + bo, bh[0], bh[1], bh[2], bh[3]);
            ldsm4(aBh + 16 * 128 + bo, bh[4], bh[5], bh[6], bh[7]);
            ldsm4(aBl + bo, bl[0], bl[1], bl[2], bl[3]);
            ldsm4(aBl + 16 * 128 + bo, bl[4], bl[5], bl[6], bl[7]);
            mma_f32(acc[0], ah, bh[0], bh[1]);
            mma_f32(acc[1], ah, bh[2], bh[3]);
            mma_f32(acc[2], ah, bh[4], bh[5]);
            mma_f32(acc[3], ah, bh[6], bh[7]);
            mma_f16(corr[0], ah, bl[0], bl[1]);
            mma_f16(corr[1], ah, bl[2], bl[3]);
            mma_f16(corr[2], ah, bl[4], bl[5]);
            mma_f16(corr[3], ah, bl[6], bl[7]);
            mma_f16(corr[0], al, bh[0], bh[1]);
            mma_f16(corr[1], al, bh[2], bh[3]);
            mma_f16(corr[2], al, bh[4], bh[5]);
            mma_f16(corr[3], al, bh[6], bh[7]);
        }
        if (CELL == 1 && i == 6) gwait(grp, gtid, wA);   // before A-stage of chunk 8 (h0-dep)
        if (i < 14) {    // A for chunk i+2: warp-local rows -> no cross-warp hazard
            stage_A<CELL>(gbase, i & 1, perm_ch<CELL>(i + 2, grp), t, p, w, lane);
            CPA_COMMIT();
        }
    }
#pragma unroll
    for (int fr = 0; fr < 4; fr++) {
        int nn = fr * 8 + 2 * (lane & 3);
        int r = 16 * w + (lane >> 2);
        float2 c01 = __half22float2(*(half2*)&corr[fr][0]);
        float2 c23 = __half22float2(*(half2*)&corr[fr][1]);
        s.As[grp][nn][r]         = acc[fr][0] + c01.x;
        s.As[grp][nn + 1][r]     = acc[fr][1] + c01.y;
        s.As[grp][nn][r + 8]     = acc[fr][2] + c23.x;
        s.As[grp][nn + 1][r + 8] = acc[fr][3] + c23.y;
    }
    __syncthreads();
}

// ---------- main persistent kernel ----------
__global__ void __launch_bounds__(NT, 1) lstm_kernel(
    const float* __restrict__ b0, const float* __restrict__ b1,
    const float* __restrict__ sw, const float* __restrict__ sb,
    float* __restrict__ out) {
    extern __shared__ __align__(1024) char dyn[];
    __shared__ SmemT s;

    const int tid = threadIdx.x, cb = blockIdx.x;
    const int j0 = cb * 8, n0 = cb * 32;

    if (tid < 64) {
        int layer = tid >> 5, c = tid & 31;
        const float* bp = layer ? b1 : b0;
        s.bias[layer][c] = bp[(c & 3) * 1024 + j0 + (c >> 2)];
    }
    if (tid < 8) s.sw8[tid] = sw[j0 + tid];
    if (tid < 128) {
#pragma unroll
        for (int jj = 0; jj < 8; jj++) {
            s.c0s[tid][jj] = 0.f; s.c1s[tid][jj] = 0.f;
            s.h0s[tid][jj] = 0.f; s.h1s[tid][jj] = 0.f;
        }
    }
    __syncthreads();

    const u32 dynb = smem_u32(dyn);

    float ut = 1.f;
    unsigned bt = 0, wA = 0, wB = 0;

#pragma unroll 1
    for (int t = 0; t < SS; t++) {
        const int p = t & 1;
        // ===== layer 0 GEMM =====
        {
            float acc[4][4] = {};
            u32 corr[4][2] = {};
            run_gemm<0>(s, t, p, n0, tid, acc, corr, dynb, 0u);
        }
        // ===== deferred skip-gate update for step t-1 (barrier B hidden under L0 GEMM) =====
        if (t > 0) {
            gbar_wait(wB);
            if (tid < 128) {
                float tot = sb[0];
                const float4* q = (const float4*)&g_sp[tid][0];
#pragma unroll
                for (int i = 0; i < 32; i++) {
                    float4 v = __ldcg(q + i);
                    tot += v.x + v.y + v.z + v.w;
                }
                float cum = sigf(tot);
                float u = rintf(ut);
                ut = (u > 0.5f) ? cum : (ut + fminf(cum, 1.f - ut));
            }
        }
        // ===== layer 0 epilogue =====
        if (tid < 128) {
            int b = tid;
            float u = rintf(ut);
#pragma unroll
            for (int jj = 0; jj < 8; jj++) {
                float ai = s.As[0][jj * 4 + 0][b] + s.As[1][jj * 4 + 0][b] + s.bias[0][jj * 4 + 0];
                float af = s.As[0][jj * 4 + 1][b] + s.As[1][jj * 4 + 1][b] + s.bias[0][jj * 4 + 1];
                float ag = s.As[0][jj * 4 + 2][b] + s.As[1][jj * 4 + 2][b] + s.bias[0][jj * 4 + 2];
                float ao = s.As[0][jj * 4 + 3][b] + s.As[1][jj * 4 + 3][b] + s.bias[0][jj * 4 + 3];
                float ig = sigf(ai);
                float fg = sigf(af);
                float gg = tanhfast(ag);
                float og = sigf(ao);
                float cn = fg * s.c0s[b][jj] + ig * gg;
                s.c0s[b][jj] = cn;
                float hn = u * (og * tanhfast(cn)) + (1.f - u) * s.h0s[b][jj];
                s.h0s[b][jj] = hn;
                __half hi = __float2half(hn);
                __stcg(&g_h0h[1 - p][(size_t)b * HH + j0 + jj], hi);
                __stcg(&g_h0l[1 - p][(size_t)b * HH + j0 + jj],
                       __float2half(hn - __half2float(hi)));
            }
        }
        gbar_arrive(); wA = ++bt;
        // ===== layer 1 GEMM (h1 chunks first; group-scoped wait for barrier A) =====
        {
            float acc[4][4] = {};
            u32 corr[4][2] = {};
            run_gemm<1>(s, t, p, n0, tid, acc, corr, dynb, wA);
        }
        // ===== layer 1 epilogue =====
        if (tid < 128) {
            int b = tid;
            float u = rintf(ut);
            float sp = 0.f;
#pragma unroll
            for (int jj = 0; jj < 8; jj++) {
                float ai = s.As[0][jj * 4 + 0][b] + s.As[1][jj * 4 + 0][b] + s.bias[1][jj * 4 + 0];
                float af = s.As[0][jj * 4 + 1][b] + s.As[1][jj * 4 + 1][b] + s.bias[1][jj * 4 + 1];
                float ag = s.As[0][jj * 4 + 2][b] + s.As[1][jj * 4 + 2][b] + s.bias[1][jj * 4 + 2];
                float ao = s.As[0][jj * 4 + 3][b] + s.As[1][jj * 4 + 3][b] + s.bias[1][jj * 4 + 3];
                float ig = sigf(ai);
                float fg = sigf(af);
                float gg = tanhfast(ag);
                float og = sigf(ao);
                float cn = fg * s.c1s[b][jj] + ig * gg;
                s.c1s[b][jj] = cn;
                sp += cn * s.sw8[jj];
                float hn = u * (og * tanhfast(cn)) + (1.f - u) * s.h1s[b][jj];
                s.h1s[b][jj] = hn;
                __half hi = __float2half(hn);
                __stcg(&g_h1h[1 - p][(size_t)b * HH + j0 + jj], hi);
                __stcg(&g_h1l[1 - p][(size_t)b * HH + j0 + jj],
                       __float2half(hn - __half2float(hi)));
                out[((size_t)b * SS + t) * HH + j0 + jj] = hn;
            }
            __stcg(&g_sp[b][cb], sp);
        }
        gbar_arrive(); wB = ++bt;
    }
}

extern "C" void kernel_launch(void* const* d_in, const int* in_sizes, int n_in,
                              void* d_out, int out_size) {
    (void)in_sizes; (void)n_in; (void)out_size;
    const float* x  = (const float*)d_in[0];
    const float* U0 = (const float*)d_in[1];
    const float* V0 = (const float*)d_in[2];
    const float* b0 = (const float*)d_in[3];
    const float* U1 = (const float*)d_in[4];
    const float* V1 = (const float*)d_in[5];
    const float* b1 = (const float*)d_in[6];
    const float* sw = (const float*)d_in[7];
    const float* sb = (const float*)d_in[8];
    float* out = (float*)d_out;

    cudaFuncSetAttribute(lstm_kernel, cudaFuncAttributeMaxDynamicSharedMemorySize, SMEM_DYN);
    conv_all<<<327680, 256>>>(U0, V0, U1, V1, x);
    lstm_kernel<<<NB, NT, SMEM_DYN>>>(b0, b1, sw, sb, out);
}